// round 1
// baseline (speedup 1.0000x reference)
#include <cuda_runtime.h>
#include <math.h>

// Problem constants: B=1, S=2048, D_MODEL=1024, H=16, D=64, G=32, n1=64, n2=2,
// TOP1=8, WIN=512, SCALE=0.125. LOD2 path is provably a no-op (top2 selects all
// 2 blocks in identity order for every query), so top-8 over scores1 directly.

#define S_LEN 2048
#define DMODEL 1024
#define NHEAD 16
#define HDIM 64
#define NEG_INF (__int_as_float(0xff800000))

// ---------------- scratch (device globals; no allocs allowed) ----------------
__device__ float g_Q[S_LEN * DMODEL];
__device__ float g_K[S_LEN * DMODEL];
__device__ float g_V[S_LEN * DMODEL];
__device__ float g_AO[S_LEN * DMODEL];
__device__ float g_K1[NHEAD * 64 * 64];
__device__ unsigned long long g_sel[NHEAD * S_LEN];

// ---------------- fp32 SGEMM: C[2048,1024] = A[2048,1024] @ B[1024,1024]^T ----
// BM=128, BN=64, BK=16, 256 threads, 8x4 micro-tile per thread.
__device__ __forceinline__ void sgemm_body(const float* __restrict__ A,
                                           const float* __restrict__ B,
                                           float* __restrict__ C) {
    __shared__ float As[16][132];
    __shared__ float Bs[16][68];
    const int tid = threadIdx.x;
    const int tx = tid & 15;   // N dir
    const int ty = tid >> 4;   // M dir
    const int m0 = blockIdx.y * 128;
    const int n0 = blockIdx.x * 64;

    float acc[8][4];
#pragma unroll
    for (int i = 0; i < 8; i++)
#pragma unroll
        for (int j = 0; j < 4; j++) acc[i][j] = 0.f;

    for (int kt = 0; kt < 1024; kt += 16) {
#pragma unroll
        for (int i = 0; i < 2; i++) {
            int fid = tid + (i << 8);            // 0..511
            int r = fid >> 2;                    // 0..127
            int c = (fid & 3) << 2;              // 0,4,8,12
            float4 v = *(const float4*)(A + (m0 + r) * 1024 + kt + c);
            As[c + 0][r] = v.x; As[c + 1][r] = v.y;
            As[c + 2][r] = v.z; As[c + 3][r] = v.w;
        }
        {
            int r = tid >> 2;                    // 0..63
            int c = (tid & 3) << 2;
            float4 v = *(const float4*)(B + (n0 + r) * 1024 + kt + c);
            Bs[c + 0][r] = v.x; Bs[c + 1][r] = v.y;
            Bs[c + 2][r] = v.z; Bs[c + 3][r] = v.w;
        }
        __syncthreads();
#pragma unroll
        for (int kk = 0; kk < 16; kk++) {
            float ar[8], br[4];
            *(float4*)&ar[0] = *(const float4*)&As[kk][ty * 8];
            *(float4*)&ar[4] = *(const float4*)&As[kk][ty * 8 + 4];
            *(float4*)&br[0] = *(const float4*)&Bs[kk][tx * 4];
#pragma unroll
            for (int i = 0; i < 8; i++)
#pragma unroll
                for (int j = 0; j < 4; j++)
                    acc[i][j] = fmaf(ar[i], br[j], acc[i][j]);
        }
        __syncthreads();
    }
#pragma unroll
    for (int i = 0; i < 8; i++) {
        float4 v = make_float4(acc[i][0], acc[i][1], acc[i][2], acc[i][3]);
        *(float4*)(C + (m0 + ty * 8 + i) * 1024 + n0 + tx * 4) = v;
    }
}

__global__ void __launch_bounds__(256) gemm_qkv_kernel(const float* __restrict__ x,
                                                       const float* __restrict__ Wq,
                                                       const float* __restrict__ Wk,
                                                       const float* __restrict__ Wv) {
    const float* B = (blockIdx.z == 0) ? Wq : (blockIdx.z == 1 ? Wk : Wv);
    float* C = (blockIdx.z == 0) ? g_Q : (blockIdx.z == 1 ? g_K : g_V);
    sgemm_body(x, B, C);
}

__global__ void __launch_bounds__(256) gemm_out_kernel(const float* __restrict__ Wo,
                                                       float* __restrict__ out) {
    sgemm_body(g_AO, Wo, out);
}

// ---------------- RoPE (in place) + fold SCALE into Q ----------------
__global__ void __launch_bounds__(256) rope_kernel() {
    int idx = blockIdx.x * 256 + threadIdx.x;       // 2048*16*32 = 1048576
    int s = idx >> 9;
    int rem = idx & 511;
    int h = rem >> 5;
    int d = rem & 31;
    float expo = (2.0f * (float)d) / 64.0f;
    float inv = 1.0f / powf(10000.0f, expo);        // match JAX fp32 formula
    float ang = (float)s * inv;
    float c, sn;
    sincosf(ang, &sn, &c);
    int base = s * DMODEL + h * HDIM + d;
    float q0 = g_Q[base], q1 = g_Q[base + 32];
    g_Q[base]      = (q0 * c - q1 * sn) * 0.125f;   // SCALE folded (top-k invariant)
    g_Q[base + 32] = (q1 * c + q0 * sn) * 0.125f;
    float k0 = g_K[base], k1 = g_K[base + 32];
    g_K[base]      = k0 * c - k1 * sn;
    g_K[base + 32] = k1 * c + k0 * sn;
}

// ---------------- LOD1 projection: k1[h][blk][o] = k_lod1[o] . Kflat[h][blk] --
// grid (16 heads, 16 block-groups of 4), 256 threads
__global__ void __launch_bounds__(256) k1_kernel(const float* __restrict__ lod1) {
    const int h = blockIdx.x, bg = blockIdx.y;
    __shared__ float Ksm[4][2048];
    const int tid = threadIdx.x;
#pragma unroll
    for (int i = 0; i < 8; i++) {
        int fid = tid + (i << 8);     // 0..2047
        int rr = fid >> 4;            // key row within group, 0..127
        int c = (fid & 15) << 2;
        float4 v = *(const float4*)(g_K + (bg * 128 + rr) * DMODEL + h * HDIM + c);
        *(float4*)&Ksm[rr >> 5][((rr & 31) << 6) + c] = v;
    }
    __syncthreads();
    const int bl = tid >> 6, o = tid & 63;
    const float4* lp = (const float4*)(lod1 + o * 2048);
    const float4* kp = (const float4*)&Ksm[bl][0];
    float acc = 0.f;
#pragma unroll 4
    for (int j = 0; j < 512; j++) {
        float4 a = lp[j], b = kp[j];
        acc += a.x * b.x + a.y * b.y + a.z * b.z + a.w * b.w;
    }
    g_K1[(h * 64 + (bg << 2) + bl) * 64 + o] = acc;
}

// ---------------- scores1 + top-8 -> 64-bit block mask ----------------
// grid (16 heads, 64 q-tiles of 32), 256 threads = 8 warps x 4 rows
__global__ void __launch_bounds__(256) top8_kernel() {
    const int h = blockIdx.x;
    const int q0 = blockIdx.y << 5;
    __shared__ float K1s[64][68];
    __shared__ float Qs[32][68];
    const int tid = threadIdx.x, lane = tid & 31, wid = tid >> 5;
    const int r0 = wid << 2;
#pragma unroll
    for (int i = 0; i < 4; i++) {
        int fid = tid + (i << 8);
        int r = fid >> 4, c = (fid & 15) << 2;
        *(float4*)&K1s[r][c] = *(const float4*)(g_K1 + (h * 64 + r) * 64 + c);
    }
#pragma unroll
    for (int i = 0; i < 2; i++) {
        int fid = tid + (i << 8);
        int r = fid >> 4, c = (fid & 15) << 2;
        *(float4*)&Qs[r][c] = *(const float4*)(g_Q + (q0 + r) * DMODEL + h * HDIM + c);
    }
    __syncthreads();
    float sc0[4] = {0, 0, 0, 0}, sc1[4] = {0, 0, 0, 0};
#pragma unroll
    for (int d4 = 0; d4 < 16; d4++) {
        float4 ka = *(const float4*)&K1s[lane][d4 << 2];
        float4 kb = *(const float4*)&K1s[lane + 32][d4 << 2];
#pragma unroll
        for (int r = 0; r < 4; r++) {
            float4 qv = *(const float4*)&Qs[r0 + r][d4 << 2];
            sc0[r] += qv.x * ka.x + qv.y * ka.y + qv.z * ka.z + qv.w * ka.w;
            sc1[r] += qv.x * kb.x + qv.y * kb.y + qv.z * kb.z + qv.w * kb.w;
        }
    }
#pragma unroll
    for (int r = 0; r < 4; r++) {
        float s0 = sc0[r], s1 = sc1[r];
        unsigned long long msk = 0ull;
#pragma unroll
        for (int it = 0; it < 8; it++) {
            float bv; int bi;
            if (s0 >= s1) { bv = s0; bi = lane; }       // tie -> lower index
            else          { bv = s1; bi = lane + 32; }
#pragma unroll
            for (int off = 16; off; off >>= 1) {
                float ov = __shfl_xor_sync(0xffffffffu, bv, off);
                int   oi = __shfl_xor_sync(0xffffffffu, bi, off);
                if (ov > bv || (ov == bv && oi < bi)) { bv = ov; bi = oi; }
            }
            msk |= 1ull << bi;
            if (bi == lane) s0 = NEG_INF;
            else if (bi == lane + 32) s1 = NEG_INF;
        }
        if (lane == 0) g_sel[h * S_LEN + q0 + r0 + r] = msk;
    }
}

// ---------------- masked flash attention ----------------
// grid (16 heads, 64 q-tiles of 32) [reversed for load balance], 256 threads.
// mask(q,k): k<=q && (q-k<512 || block-bit(k>>5) set). Skip kv-tiles not needed
// by any row (outside window union and not in union of selection bitmasks).
__global__ void __launch_bounds__(256) attn_kernel() {
    const int h = blockIdx.x;
    const int qt = 63 - blockIdx.y;          // heavy tiles first
    const int q0 = qt << 5;
    __shared__ float Qs[32][68];
    __shared__ float Ks[32][68];
    __shared__ float Vs[32][68];
    __shared__ float Ps[32][33];
    __shared__ unsigned long long Ssel[32];
    __shared__ unsigned long long s_uni;
    const int tid = threadIdx.x, lane = tid & 31, wid = tid >> 5;
    const int r0 = wid << 2;

#pragma unroll
    for (int i = 0; i < 2; i++) {
        int fid = tid + (i << 8);
        int r = fid >> 4, c = (fid & 15) << 2;
        *(float4*)&Qs[r][c] = *(const float4*)(g_Q + (q0 + r) * DMODEL + h * HDIM + c);
    }
    if (tid < 32) Ssel[tid] = g_sel[h * S_LEN + q0 + tid];
    __syncthreads();
    if (tid == 0) {
        unsigned long long u = 0;
        for (int r = 0; r < 32; r++) u |= Ssel[r];
        s_uni = u;
    }
    __syncthreads();
    const unsigned long long uni = s_uni;
    const int wlo = (q0 >= 512) ? ((q0 - 511) >> 5) : 0;

    float m[4], l[4];
    float2 acc[4];
#pragma unroll
    for (int r = 0; r < 4; r++) { m[r] = NEG_INF; l[r] = 0.f; acc[r] = make_float2(0.f, 0.f); }

    for (int tk = 0; tk <= qt; tk++) {
        if (tk < wlo && !((uni >> tk) & 1ull)) continue;   // block-uniform skip
        __syncthreads();
#pragma unroll
        for (int i = 0; i < 2; i++) {
            int fid = tid + (i << 8);
            int r = fid >> 4, c = (fid & 15) << 2;
            int gro = ((tk << 5) + r) * DMODEL + h * HDIM + c;
            *(float4*)&Ks[r][c] = *(const float4*)(g_K + gro);
            *(float4*)&Vs[r][c] = *(const float4*)(g_V + gro);
        }
        __syncthreads();

        float s[4] = {0, 0, 0, 0};
#pragma unroll
        for (int d4 = 0; d4 < 16; d4++) {
            float4 kv = *(const float4*)&Ks[lane][d4 << 2];
#pragma unroll
            for (int r = 0; r < 4; r++) {
                float4 qv = *(const float4*)&Qs[r0 + r][d4 << 2];
                s[r] += qv.x * kv.x + qv.y * kv.y + qv.z * kv.z + qv.w * kv.w;
            }
        }
        const int k = (tk << 5) + lane;
#pragma unroll
        for (int r = 0; r < 4; r++) {
            const int q = q0 + r0 + r;
            bool ok = (k <= q) && ((q - k) < 512 || ((Ssel[r0 + r] >> tk) & 1ull));
            float sv = ok ? s[r] : NEG_INF;
            float mx = sv;
#pragma unroll
            for (int off = 16; off; off >>= 1)
                mx = fmaxf(mx, __shfl_xor_sync(0xffffffffu, mx, off));
            float mn = fmaxf(m[r], mx);
            float p, cf;
            if (mn == NEG_INF) { p = 0.f; cf = 1.f; }
            else { cf = expf(m[r] - mn); p = expf(sv - mn); }
            m[r] = mn;
            float ps = p;
#pragma unroll
            for (int off = 16; off; off >>= 1)
                ps += __shfl_xor_sync(0xffffffffu, ps, off);
            l[r] = l[r] * cf + ps;
            acc[r].x *= cf; acc[r].y *= cf;
            Ps[r0 + r][lane] = p;
        }
        __syncwarp();
#pragma unroll 8
        for (int kk = 0; kk < 32; kk++) {
            float2 v = *(const float2*)&Vs[kk][lane << 1];
#pragma unroll
            for (int r = 0; r < 4; r++) {
                float p = Ps[r0 + r][kk];
                acc[r].x = fmaf(p, v.x, acc[r].x);
                acc[r].y = fmaf(p, v.y, acc[r].y);
            }
        }
    }
#pragma unroll
    for (int r = 0; r < 4; r++) {
        float inv = 1.0f / l[r];   // diagonal always attended -> l >= 1
        float2 o = make_float2(acc[r].x * inv, acc[r].y * inv);
        *(float2*)(g_AO + (q0 + r0 + r) * DMODEL + h * HDIM + (lane << 1)) = o;
    }
}

// ---------------- launch ----------------
extern "C" void kernel_launch(void* const* d_in, const int* in_sizes, int n_in,
                              void* d_out, int out_size) {
    const float* x    = (const float*)d_in[0];
    const float* Wq   = (const float*)d_in[1];
    const float* Wk   = (const float*)d_in[2];
    const float* Wv   = (const float*)d_in[3];
    const float* Wo   = (const float*)d_in[4];
    const float* lod1 = (const float*)d_in[5];
    // d_in[6..8] (v_lod1, k_lod2, v_lod2) are dead in the reference.

    gemm_qkv_kernel<<<dim3(16, 16, 3), 256>>>(x, Wq, Wk, Wv);
    rope_kernel<<<4096, 256>>>();
    k1_kernel<<<dim3(16, 16), 256>>>(lod1);
    top8_kernel<<<dim3(16, 64), 256>>>();
    attn_kernel<<<dim3(16, 64), 256>>>();
    gemm_out_kernel<<<dim3(16, 16), 256>>>(Wo, (float*)d_out);
}

// round 8
// speedup vs baseline: 1.0728x; 1.0728x over previous
#include <cuda_runtime.h>
#include <math.h>

// Problem constants: B=1, S=2048, D_MODEL=1024, H=16, D=64, G=32, n1=64, n2=2,
// TOP1=8, WIN=512, SCALE=0.125. LOD2 path is provably a no-op, so top-8 over
// scores1 directly. GEMMs now run on tensor cores: tf32x3 (hi/lo split) via
// mma.sync.m16n8k8 -> fp32-equivalent accuracy (~2^-22 rel err).

#define S_LEN 2048
#define DMODEL 1024
#define NHEAD 16
#define HDIM 64
#define NEG_INF (__int_as_float(0xff800000))

// ---------------- scratch (device globals; no allocs allowed) ----------------
__device__ float g_Q[S_LEN * DMODEL];
__device__ float g_K[S_LEN * DMODEL];
__device__ float g_V[S_LEN * DMODEL];
__device__ float g_AO[S_LEN * DMODEL];
__device__ float g_K1[NHEAD * 64 * 64];
__device__ unsigned long long g_sel[NHEAD * S_LEN];

// ---------------- tf32 helpers ----------------
__device__ __forceinline__ unsigned tf32_of(float x) {
    unsigned u;
    asm("cvt.rna.tf32.f32 %0, %1;" : "=r"(u) : "f"(x));
    return u;
}
__device__ __forceinline__ void split_tf32(float x, float& hi, float& lo) {
    unsigned uh = tf32_of(x);
    hi = __uint_as_float(uh);
    lo = __uint_as_float(tf32_of(x - hi));
}
__device__ __forceinline__ void split4(float4 v, float4& h, float4& l) {
    split_tf32(v.x, h.x, l.x);
    split_tf32(v.y, h.y, l.y);
    split_tf32(v.z, h.z, l.z);
    split_tf32(v.w, h.w, l.w);
}

#define MMA_TF32(Cf, Au, Bu)                                                  \
    asm volatile(                                                             \
        "mma.sync.aligned.m16n8k8.row.col.f32.tf32.tf32.f32 "                 \
        "{%0,%1,%2,%3}, {%4,%5,%6,%7}, {%8,%9}, {%0,%1,%2,%3};"               \
        : "+f"(Cf[0]), "+f"(Cf[1]), "+f"(Cf[2]), "+f"(Cf[3])                  \
        : "r"(Au[0]), "r"(Au[1]), "r"(Au[2]), "r"(Au[3]),                     \
          "r"(Bu[0]), "r"(Bu[1]))

// ---------------- tensor-core SGEMM (tf32x3) ----------------
// C[2048,1024] = A[2048,1024] @ B[1024,1024]^T
// BM=128, BN=64, BK=16, 256 threads = 8 warps (4 My x 2 Nx), warp tile 32x32.
__device__ __forceinline__ void sgemm_body(const float* __restrict__ A,
                                           const float* __restrict__ B,
                                           float* __restrict__ C) {
    __shared__ float Ah[128][20], Al[128][20], Bh[64][20], Bl[64][20];
    const int tid = threadIdx.x;
    const int lane = tid & 31, warp = tid >> 5;
    const int wy = warp >> 1, wx = warp & 1;
    const int m0 = blockIdx.y * 128, n0 = blockIdx.x * 64;
    const int mw = wy * 32, nw = wx * 32;
    const int gr = tid >> 2;            // 0..63
    const int gc = (tid & 3) << 2;      // 0,4,8,12

    float acc[2][4][4];
#pragma unroll
    for (int i = 0; i < 2; i++)
#pragma unroll
        for (int j = 0; j < 4; j++)
#pragma unroll
            for (int e = 0; e < 4; e++) acc[i][j][e] = 0.f;

    float4 pa0, pa1, pb;
    // prologue: tile 0
    pa0 = *(const float4*)(A + (m0 + gr) * 1024 + gc);
    pa1 = *(const float4*)(A + (m0 + 64 + gr) * 1024 + gc);
    pb  = *(const float4*)(B + (n0 + gr) * 1024 + gc);
    {
        float4 h, l;
        split4(pa0, h, l); *(float4*)&Ah[gr][gc] = h;      *(float4*)&Al[gr][gc] = l;
        split4(pa1, h, l); *(float4*)&Ah[gr + 64][gc] = h; *(float4*)&Al[gr + 64][gc] = l;
        split4(pb, h, l);  *(float4*)&Bh[gr][gc] = h;      *(float4*)&Bl[gr][gc] = l;
    }
    __syncthreads();

    const int row = lane >> 2, col = lane & 3;

    for (int kt = 0; kt < 1024; kt += 16) {
        const bool more = (kt + 16) < 1024;
        if (more) {
            pa0 = *(const float4*)(A + (m0 + gr) * 1024 + kt + 16 + gc);
            pa1 = *(const float4*)(A + (m0 + 64 + gr) * 1024 + kt + 16 + gc);
            pb  = *(const float4*)(B + (n0 + gr) * 1024 + kt + 16 + gc);
        }
#pragma unroll
        for (int ks = 0; ks < 16; ks += 8) {
            unsigned ah[2][4], al2[2][4], bh[4][2], bl2[4][2];
#pragma unroll
            for (int i = 0; i < 2; i++) {
                const int m = mw + i * 16 + row;
                ah[i][0] = __float_as_uint(Ah[m][ks + col]);
                ah[i][1] = __float_as_uint(Ah[m + 8][ks + col]);
                ah[i][2] = __float_as_uint(Ah[m][ks + col + 4]);
                ah[i][3] = __float_as_uint(Ah[m + 8][ks + col + 4]);
                al2[i][0] = __float_as_uint(Al[m][ks + col]);
                al2[i][1] = __float_as_uint(Al[m + 8][ks + col]);
                al2[i][2] = __float_as_uint(Al[m][ks + col + 4]);
                al2[i][3] = __float_as_uint(Al[m + 8][ks + col + 4]);
            }
#pragma unroll
            for (int j = 0; j < 4; j++) {
                const int n = nw + j * 8 + row;
                bh[j][0] = __float_as_uint(Bh[n][ks + col]);
                bh[j][1] = __float_as_uint(Bh[n][ks + col + 4]);
                bl2[j][0] = __float_as_uint(Bl[n][ks + col]);
                bl2[j][1] = __float_as_uint(Bl[n][ks + col + 4]);
            }
#pragma unroll
            for (int i = 0; i < 2; i++)
#pragma unroll
                for (int j = 0; j < 4; j++) {
                    MMA_TF32(acc[i][j], ah[i], bh[j]);
                    MMA_TF32(acc[i][j], al2[i], bh[j]);
                    MMA_TF32(acc[i][j], ah[i], bl2[j]);
                }
        }
        __syncthreads();
        if (more) {
            float4 h, l;
            split4(pa0, h, l); *(float4*)&Ah[gr][gc] = h;      *(float4*)&Al[gr][gc] = l;
            split4(pa1, h, l); *(float4*)&Ah[gr + 64][gc] = h; *(float4*)&Al[gr + 64][gc] = l;
            split4(pb, h, l);  *(float4*)&Bh[gr][gc] = h;      *(float4*)&Bl[gr][gc] = l;
            __syncthreads();
        }
    }

    const int col2 = (lane & 3) << 1;
#pragma unroll
    for (int i = 0; i < 2; i++)
#pragma unroll
        for (int j = 0; j < 4; j++) {
            float* cp = C + (m0 + mw + i * 16 + row) * 1024 + n0 + nw + j * 8 + col2;
            *(float2*)cp = make_float2(acc[i][j][0], acc[i][j][1]);
            *(float2*)(cp + 8 * 1024) = make_float2(acc[i][j][2], acc[i][j][3]);
        }
}

__global__ void __launch_bounds__(256, 2) gemm_qkv_kernel(const float* __restrict__ x,
                                                          const float* __restrict__ Wq,
                                                          const float* __restrict__ Wk,
                                                          const float* __restrict__ Wv) {
    const float* B = (blockIdx.z == 0) ? Wq : (blockIdx.z == 1 ? Wk : Wv);
    float* C = (blockIdx.z == 0) ? g_Q : (blockIdx.z == 1 ? g_K : g_V);
    sgemm_body(x, B, C);
}

__global__ void __launch_bounds__(256, 2) gemm_out_kernel(const float* __restrict__ Wo,
                                                          float* __restrict__ out) {
    sgemm_body(g_AO, Wo, out);
}

// ---------------- RoPE (in place) + fold SCALE into Q ----------------
__global__ void __launch_bounds__(256) rope_kernel() {
    int idx = blockIdx.x * 256 + threadIdx.x;       // 2048*16*32 = 1048576
    int s = idx >> 9;
    int rem = idx & 511;
    int h = rem >> 5;
    int d = rem & 31;
    float expo = (2.0f * (float)d) / 64.0f;
    float inv = 1.0f / powf(10000.0f, expo);        // match JAX fp32 formula
    float ang = (float)s * inv;
    float c, sn;
    sincosf(ang, &sn, &c);
    int base = s * DMODEL + h * HDIM + d;
    float q0 = g_Q[base], q1 = g_Q[base + 32];
    g_Q[base]      = (q0 * c - q1 * sn) * 0.125f;   // SCALE folded (top-k invariant)
    g_Q[base + 32] = (q1 * c + q0 * sn) * 0.125f;
    float k0 = g_K[base], k1 = g_K[base + 32];
    g_K[base]      = k0 * c - k1 * sn;
    g_K[base + 32] = k1 * c + k0 * sn;
}

// ---------------- LOD1 projection: k1[h][blk][o] = k_lod1[o] . Kflat[h][blk] --
// grid (16 heads, 16 block-groups of 4), 256 threads
__global__ void __launch_bounds__(256) k1_kernel(const float* __restrict__ lod1) {
    const int h = blockIdx.x, bg = blockIdx.y;
    __shared__ float Ksm[4][2048];
    const int tid = threadIdx.x;
#pragma unroll
    for (int i = 0; i < 8; i++) {
        int fid = tid + (i << 8);     // 0..2047
        int rr = fid >> 4;            // key row within group, 0..127
        int c = (fid & 15) << 2;
        float4 v = *(const float4*)(g_K + (bg * 128 + rr) * DMODEL + h * HDIM + c);
        *(float4*)&Ksm[rr >> 5][((rr & 31) << 6) + c] = v;
    }
    __syncthreads();
    const int bl = tid >> 6, o = tid & 63;
    const float4* lp = (const float4*)(lod1 + o * 2048);
    const float4* kp = (const float4*)&Ksm[bl][0];
    float acc = 0.f;
#pragma unroll 4
    for (int j = 0; j < 512; j++) {
        float4 a = lp[j], b = kp[j];
        acc += a.x * b.x + a.y * b.y + a.z * b.z + a.w * b.w;
    }
    g_K1[(h * 64 + (bg << 2) + bl) * 64 + o] = acc;
}

// ---------------- scores1 + top-8 -> 64-bit block mask ----------------
// grid (16 heads, 64 q-tiles of 32), 256 threads = 8 warps x 4 rows
__global__ void __launch_bounds__(256) top8_kernel() {
    const int h = blockIdx.x;
    const int q0 = blockIdx.y << 5;
    __shared__ float K1s[64][68];
    __shared__ float Qs[32][68];
    const int tid = threadIdx.x, lane = tid & 31, wid = tid >> 5;
    const int r0 = wid << 2;
#pragma unroll
    for (int i = 0; i < 4; i++) {
        int fid = tid + (i << 8);
        int r = fid >> 4, c = (fid & 15) << 2;
        *(float4*)&K1s[r][c] = *(const float4*)(g_K1 + (h * 64 + r) * 64 + c);
    }
#pragma unroll
    for (int i = 0; i < 2; i++) {
        int fid = tid + (i << 8);
        int r = fid >> 4, c = (fid & 15) << 2;
        *(float4*)&Qs[r][c] = *(const float4*)(g_Q + (q0 + r) * DMODEL + h * HDIM + c);
    }
    __syncthreads();
    float sc0[4] = {0, 0, 0, 0}, sc1[4] = {0, 0, 0, 0};
#pragma unroll
    for (int d4 = 0; d4 < 16; d4++) {
        float4 ka = *(const float4*)&K1s[lane][d4 << 2];
        float4 kb = *(const float4*)&K1s[lane + 32][d4 << 2];
#pragma unroll
        for (int r = 0; r < 4; r++) {
            float4 qv = *(const float4*)&Qs[r0 + r][d4 << 2];
            sc0[r] += qv.x * ka.x + qv.y * ka.y + qv.z * ka.z + qv.w * ka.w;
            sc1[r] += qv.x * kb.x + qv.y * kb.y + qv.z * kb.z + qv.w * kb.w;
        }
    }
#pragma unroll
    for (int r = 0; r < 4; r++) {
        float s0 = sc0[r], s1 = sc1[r];
        unsigned long long msk = 0ull;
#pragma unroll
        for (int it = 0; it < 8; it++) {
            float bv; int bi;
            if (s0 >= s1) { bv = s0; bi = lane; }       // tie -> lower index
            else          { bv = s1; bi = lane + 32; }
#pragma unroll
            for (int off = 16; off; off >>= 1) {
                float ov = __shfl_xor_sync(0xffffffffu, bv, off);
                int   oi = __shfl_xor_sync(0xffffffffu, bi, off);
                if (ov > bv || (ov == bv && oi < bi)) { bv = ov; bi = oi; }
            }
            msk |= 1ull << bi;
            if (bi == lane) s0 = NEG_INF;
            else if (bi == lane + 32) s1 = NEG_INF;
        }
        if (lane == 0) g_sel[h * S_LEN + q0 + r0 + r] = msk;
    }
}

// ---------------- masked flash attention ----------------
// grid (16 heads, 64 q-tiles of 32) [reversed for load balance], 256 threads.
// mask(q,k): k<=q && (q-k<512 || block-bit(k>>5) set). Skip kv-tiles not needed
// by any row (outside window union and not in union of selection bitmasks).
__global__ void __launch_bounds__(256) attn_kernel() {
    const int h = blockIdx.x;
    const int qt = 63 - blockIdx.y;          // heavy tiles first
    const int q0 = qt << 5;
    __shared__ float Qs[32][68];
    __shared__ float Ks[32][68];
    __shared__ float Vs[32][68];
    __shared__ float Ps[32][33];
    __shared__ unsigned long long Ssel[32];
    __shared__ unsigned long long s_uni;
    const int tid = threadIdx.x, lane = tid & 31, wid = tid >> 5;
    const int r0 = wid << 2;

#pragma unroll
    for (int i = 0; i < 2; i++) {
        int fid = tid + (i << 8);
        int r = fid >> 4, c = (fid & 15) << 2;
        *(float4*)&Qs[r][c] = *(const float4*)(g_Q + (q0 + r) * DMODEL + h * HDIM + c);
    }
    if (tid < 32) Ssel[tid] = g_sel[h * S_LEN + q0 + tid];
    __syncthreads();
    if (tid == 0) {
        unsigned long long u = 0;
        for (int r = 0; r < 32; r++) u |= Ssel[r];
        s_uni = u;
    }
    __syncthreads();
    const unsigned long long uni = s_uni;
    const int wlo = (q0 >= 512) ? ((q0 - 511) >> 5) : 0;

    float m[4], l[4];
    float2 acc[4];
#pragma unroll
    for (int r = 0; r < 4; r++) { m[r] = NEG_INF; l[r] = 0.f; acc[r] = make_float2(0.f, 0.f); }

    for (int tk = 0; tk <= qt; tk++) {
        if (tk < wlo && !((uni >> tk) & 1ull)) continue;   // block-uniform skip
        __syncthreads();
#pragma unroll
        for (int i = 0; i < 2; i++) {
            int fid = tid + (i << 8);
            int r = fid >> 4, c = (fid & 15) << 2;
            int gro = ((tk << 5) + r) * DMODEL + h * HDIM + c;
            *(float4*)&Ks[r][c] = *(const float4*)(g_K + gro);
            *(float4*)&Vs[r][c] = *(const float4*)(g_V + gro);
        }
        __syncthreads();

        float s[4] = {0, 0, 0, 0};
#pragma unroll
        for (int d4 = 0; d4 < 16; d4++) {
            float4 kv = *(const float4*)&Ks[lane][d4 << 2];
#pragma unroll
            for (int r = 0; r < 4; r++) {
                float4 qv = *(const float4*)&Qs[r0 + r][d4 << 2];
                s[r] += qv.x * kv.x + qv.y * kv.y + qv.z * kv.z + qv.w * kv.w;
            }
        }
        const int k = (tk << 5) + lane;
#pragma unroll
        for (int r = 0; r < 4; r++) {
            const int q = q0 + r0 + r;
            bool ok = (k <= q) && ((q - k) < 512 || ((Ssel[r0 + r] >> tk) & 1ull));
            float sv = ok ? s[r] : NEG_INF;
            float mx = sv;
#pragma unroll
            for (int off = 16; off; off >>= 1)
                mx = fmaxf(mx, __shfl_xor_sync(0xffffffffu, mx, off));
            float mn = fmaxf(m[r], mx);
            float p, cf;
            if (mn == NEG_INF) { p = 0.f; cf = 1.f; }
            else { cf = expf(m[r] - mn); p = expf(sv - mn); }
            m[r] = mn;
            float ps = p;
#pragma unroll
            for (int off = 16; off; off >>= 1)
                ps += __shfl_xor_sync(0xffffffffu, ps, off);
            l[r] = l[r] * cf + ps;
            acc[r].x *= cf; acc[r].y *= cf;
            Ps[r0 + r][lane] = p;
        }
        __syncwarp();
#pragma unroll 8
        for (int kk = 0; kk < 32; kk++) {
            float2 v = *(const float2*)&Vs[kk][lane << 1];
#pragma unroll
            for (int r = 0; r < 4; r++) {
                float p = Ps[r0 + r][kk];
                acc[r].x = fmaf(p, v.x, acc[r].x);
                acc[r].y = fmaf(p, v.y, acc[r].y);
            }
        }
    }
#pragma unroll
    for (int r = 0; r < 4; r++) {
        float inv = 1.0f / l[r];   // diagonal always attended -> l >= 1
        float2 o = make_float2(acc[r].x * inv, acc[r].y * inv);
        *(float2*)(g_AO + (q0 + r0 + r) * DMODEL + h * HDIM + (lane << 1)) = o;
    }
}

// ---------------- launch ----------------
extern "C" void kernel_launch(void* const* d_in, const int* in_sizes, int n_in,
                              void* d_out, int out_size) {
    const float* x    = (const float*)d_in[0];
    const float* Wq   = (const float*)d_in[1];
    const float* Wk   = (const float*)d_in[2];
    const float* Wv   = (const float*)d_in[3];
    const float* Wo   = (const float*)d_in[4];
    const float* lod1 = (const float*)d_in[5];
    // d_in[6..8] (v_lod1, k_lod2, v_lod2) are dead in the reference.

    gemm_qkv_kernel<<<dim3(16, 16, 3), 256>>>(x, Wq, Wk, Wv);
    rope_kernel<<<4096, 256>>>();
    k1_kernel<<<dim3(16, 16), 256>>>(lod1);
    top8_kernel<<<dim3(16, 64), 256>>>();
    attn_kernel<<<dim3(16, 64), 256>>>();
    gemm_out_kernel<<<dim3(16, 16), 256>>>(Wo, (float*)d_out);
}

// round 9
// speedup vs baseline: 1.2874x; 1.2000x over previous
#include <cuda_runtime.h>
#include <cuda_bf16.h>
#include <math.h>

// B=1, S=2048, D_MODEL=1024, H=16, D=64, G=32, n1=64, n2=2, TOP1=8, WIN=512,
// SCALE=0.125. LOD2 path provably a no-op -> top-8 over scores1 directly.
// GEMMs: bf16x2 hi/lo split via mma.sync.m16n8k16 (3 mmas per K=16);
// dropped al*bl term ~2^-16 relative error -> far inside the 1e-3 budget
// (measured tf32x3 baseline rel_err 1.6e-5).

#define S_LEN 2048
#define DMODEL 1024
#define NHEAD 16
#define HDIM 64
#define NEG_INF (__int_as_float(0xff800000))

// ---------------- scratch (device globals; no allocs allowed) ----------------
__device__ float g_Q[S_LEN * DMODEL];
__device__ float g_K[S_LEN * DMODEL];
__device__ float g_V[S_LEN * DMODEL];
__device__ float g_AO[S_LEN * DMODEL];
__device__ float g_K1[NHEAD * 64 * 64];
__device__ unsigned long long g_sel[NHEAD * S_LEN];

// ---------------- bf16 split helpers ----------------
// x = hi + lo with hi = bf16(x), lo = bf16(x - hi): ~16 mantissa bits total.
__device__ __forceinline__ void bsplit2(float x0, float x1,
                                        unsigned& hi, unsigned& lo) {
    __nv_bfloat16 h0 = __float2bfloat16(x0);
    __nv_bfloat16 h1 = __float2bfloat16(x1);
    __nv_bfloat16 l0 = __float2bfloat16(x0 - __bfloat162float(h0));
    __nv_bfloat16 l1 = __float2bfloat16(x1 - __bfloat162float(h1));
    hi = ((unsigned)__bfloat16_as_ushort(h1) << 16) | (unsigned)__bfloat16_as_ushort(h0);
    lo = ((unsigned)__bfloat16_as_ushort(l1) << 16) | (unsigned)__bfloat16_as_ushort(l0);
}

#define MMA_BF16(Cf, Au, Bu)                                                  \
    asm volatile(                                                             \
        "mma.sync.aligned.m16n8k16.row.col.f32.bf16.bf16.f32 "                \
        "{%0,%1,%2,%3}, {%4,%5,%6,%7}, {%8,%9}, {%0,%1,%2,%3};"               \
        : "+f"(Cf[0]), "+f"(Cf[1]), "+f"(Cf[2]), "+f"(Cf[3])                  \
        : "r"(Au[0]), "r"(Au[1]), "r"(Au[2]), "r"(Au[3]),                     \
          "r"(Bu[0]), "r"(Bu[1]))

// ---------------- tensor-core SGEMM (bf16x2 split) ----------------
// C[2048,1024] = A[2048,1024] @ B[1024,1024]^T
// BM=128, BN=64, BK=16, 256 threads = 8 warps (4 My x 2 Nx), warp tile 32x32.
// SMEM rows hold 8 packed-bf16x2 uints (K=16) padded to stride 12 ->
// fragment LDS pattern {12g+t} hits 32 distinct banks (conflict-free).
__device__ __forceinline__ void sgemm_body(const float* __restrict__ A,
                                           const float* __restrict__ B,
                                           float* __restrict__ C) {
    __shared__ unsigned Ah[128][12], Al[128][12], Bh[64][12], Bl[64][12];
    const int tid = threadIdx.x;
    const int lane = tid & 31, warp = tid >> 5;
    const int wy = warp >> 1, wx = warp & 1;
    const int m0 = blockIdx.y * 128, n0 = blockIdx.x * 64;
    const int mw = wy * 32, nw = wx * 32;
    const int gr = tid >> 2;            // 0..63
    const int gc = (tid & 3) << 2;      // float col: 0,4,8,12
    const int gu = (tid & 3) << 1;      // uint col:  0,2,4,6

    float acc[2][4][4];
#pragma unroll
    for (int i = 0; i < 2; i++)
#pragma unroll
        for (int j = 0; j < 4; j++)
#pragma unroll
            for (int e = 0; e < 4; e++) acc[i][j][e] = 0.f;

    float4 pa0, pa1, pb;
    pa0 = *(const float4*)(A + (m0 + gr) * 1024 + gc);
    pa1 = *(const float4*)(A + (m0 + 64 + gr) * 1024 + gc);
    pb  = *(const float4*)(B + (n0 + gr) * 1024 + gc);
    {
        unsigned h0, l0, h1, l1;
        bsplit2(pa0.x, pa0.y, h0, l0); bsplit2(pa0.z, pa0.w, h1, l1);
        *(uint2*)&Ah[gr][gu] = make_uint2(h0, h1);
        *(uint2*)&Al[gr][gu] = make_uint2(l0, l1);
        bsplit2(pa1.x, pa1.y, h0, l0); bsplit2(pa1.z, pa1.w, h1, l1);
        *(uint2*)&Ah[gr + 64][gu] = make_uint2(h0, h1);
        *(uint2*)&Al[gr + 64][gu] = make_uint2(l0, l1);
        bsplit2(pb.x, pb.y, h0, l0); bsplit2(pb.z, pb.w, h1, l1);
        *(uint2*)&Bh[gr][gu] = make_uint2(h0, h1);
        *(uint2*)&Bl[gr][gu] = make_uint2(l0, l1);
    }
    __syncthreads();

    const int g = lane >> 2, t = lane & 3;

    for (int kt = 0; kt < 1024; kt += 16) {
        const bool more = (kt + 16) < 1024;
        if (more) {
            pa0 = *(const float4*)(A + (m0 + gr) * 1024 + kt + 16 + gc);
            pa1 = *(const float4*)(A + (m0 + 64 + gr) * 1024 + kt + 16 + gc);
            pb  = *(const float4*)(B + (n0 + gr) * 1024 + kt + 16 + gc);
        }
        // m16n8k16 fragments: A row g(/g+8), k-pair t (k 2t,2t+1) and t+4.
        unsigned ah[2][4], al2[2][4], bh[4][2], bl2[4][2];
#pragma unroll
        for (int i = 0; i < 2; i++) {
            const int m = mw + i * 16 + g;
            ah[i][0] = Ah[m][t];      ah[i][1] = Ah[m + 8][t];
            ah[i][2] = Ah[m][t + 4];  ah[i][3] = Ah[m + 8][t + 4];
            al2[i][0] = Al[m][t];     al2[i][1] = Al[m + 8][t];
            al2[i][2] = Al[m][t + 4]; al2[i][3] = Al[m + 8][t + 4];
        }
#pragma unroll
        for (int j = 0; j < 4; j++) {
            const int n = nw + j * 8 + g;
            bh[j][0] = Bh[n][t];  bh[j][1] = Bh[n][t + 4];
            bl2[j][0] = Bl[n][t]; bl2[j][1] = Bl[n][t + 4];
        }
#pragma unroll
        for (int i = 0; i < 2; i++)
#pragma unroll
            for (int j = 0; j < 4; j++) {
                MMA_BF16(acc[i][j], ah[i], bh[j]);
                MMA_BF16(acc[i][j], al2[i], bh[j]);
                MMA_BF16(acc[i][j], ah[i], bl2[j]);
            }
        __syncthreads();
        if (more) {
            unsigned h0, l0, h1, l1;
            bsplit2(pa0.x, pa0.y, h0, l0); bsplit2(pa0.z, pa0.w, h1, l1);
            *(uint2*)&Ah[gr][gu] = make_uint2(h0, h1);
            *(uint2*)&Al[gr][gu] = make_uint2(l0, l1);
            bsplit2(pa1.x, pa1.y, h0, l0); bsplit2(pa1.z, pa1.w, h1, l1);
            *(uint2*)&Ah[gr + 64][gu] = make_uint2(h0, h1);
            *(uint2*)&Al[gr + 64][gu] = make_uint2(l0, l1);
            bsplit2(pb.x, pb.y, h0, l0); bsplit2(pb.z, pb.w, h1, l1);
            *(uint2*)&Bh[gr][gu] = make_uint2(h0, h1);
            *(uint2*)&Bl[gr][gu] = make_uint2(l0, l1);
            __syncthreads();
        }
    }

    const int col2 = (lane & 3) << 1;
#pragma unroll
    for (int i = 0; i < 2; i++)
#pragma unroll
        for (int j = 0; j < 4; j++) {
            float* cp = C + (m0 + mw + i * 16 + g) * 1024 + n0 + nw + j * 8 + col2;
            *(float2*)cp = make_float2(acc[i][j][0], acc[i][j][1]);
            *(float2*)(cp + 8 * 1024) = make_float2(acc[i][j][2], acc[i][j][3]);
        }
}

__global__ void __launch_bounds__(256, 2) gemm_qkv_kernel(const float* __restrict__ x,
                                                          const float* __restrict__ Wq,
                                                          const float* __restrict__ Wk,
                                                          const float* __restrict__ Wv) {
    const float* B = (blockIdx.z == 0) ? Wq : (blockIdx.z == 1 ? Wk : Wv);
    float* C = (blockIdx.z == 0) ? g_Q : (blockIdx.z == 1 ? g_K : g_V);
    sgemm_body(x, B, C);
}

__global__ void __launch_bounds__(256, 2) gemm_out_kernel(const float* __restrict__ Wo,
                                                          float* __restrict__ out) {
    sgemm_body(g_AO, Wo, out);
}

// ---------------- RoPE (in place) + fold SCALE into Q ----------------
__global__ void __launch_bounds__(256) rope_kernel() {
    int idx = blockIdx.x * 256 + threadIdx.x;       // 2048*16*32 = 1048576
    int s = idx >> 9;
    int rem = idx & 511;
    int h = rem >> 5;
    int d = rem & 31;
    float expo = (2.0f * (float)d) / 64.0f;
    float inv = 1.0f / powf(10000.0f, expo);        // match JAX fp32 formula
    float ang = (float)s * inv;
    float c, sn;
    sincosf(ang, &sn, &c);
    int base = s * DMODEL + h * HDIM + d;
    float q0 = g_Q[base], q1 = g_Q[base + 32];
    g_Q[base]      = (q0 * c - q1 * sn) * 0.125f;   // SCALE folded (top-k invariant)
    g_Q[base + 32] = (q1 * c + q0 * sn) * 0.125f;
    float k0 = g_K[base], k1 = g_K[base + 32];
    g_K[base]      = k0 * c - k1 * sn;
    g_K[base + 32] = k1 * c + k0 * sn;
}

// ---------------- LOD1 projection: k1[h][blk][o] = k_lod1[o] . Kflat[h][blk] --
// grid (16 heads, 16 block-groups of 4), 256 threads
__global__ void __launch_bounds__(256) k1_kernel(const float* __restrict__ lod1) {
    const int h = blockIdx.x, bg = blockIdx.y;
    __shared__ float Ksm[4][2048];
    const int tid = threadIdx.x;
#pragma unroll
    for (int i = 0; i < 8; i++) {
        int fid = tid + (i << 8);     // 0..2047
        int rr = fid >> 4;            // key row within group, 0..127
        int c = (fid & 15) << 2;
        float4 v = *(const float4*)(g_K + (bg * 128 + rr) * DMODEL + h * HDIM + c);
        *(float4*)&Ksm[rr >> 5][((rr & 31) << 6) + c] = v;
    }
    __syncthreads();
    const int bl = tid >> 6, o = tid & 63;
    const float4* lp = (const float4*)(lod1 + o * 2048);
    const float4* kp = (const float4*)&Ksm[bl][0];
    float acc = 0.f;
#pragma unroll 4
    for (int j = 0; j < 512; j++) {
        float4 a = lp[j], b = kp[j];
        acc += a.x * b.x + a.y * b.y + a.z * b.z + a.w * b.w;
    }
    g_K1[(h * 64 + (bg << 2) + bl) * 64 + o] = acc;
}

// ---------------- scores1 + top-8 -> 64-bit block mask ----------------
// grid (16 heads, 64 q-tiles of 32), 256 threads = 8 warps x 4 rows
__global__ void __launch_bounds__(256) top8_kernel() {
    const int h = blockIdx.x;
    const int q0 = blockIdx.y << 5;
    __shared__ float K1s[64][68];
    __shared__ float Qs[32][68];
    const int tid = threadIdx.x, lane = tid & 31, wid = tid >> 5;
    const int r0 = wid << 2;
#pragma unroll
    for (int i = 0; i < 4; i++) {
        int fid = tid + (i << 8);
        int r = fid >> 4, c = (fid & 15) << 2;
        *(float4*)&K1s[r][c] = *(const float4*)(g_K1 + (h * 64 + r) * 64 + c);
    }
#pragma unroll
    for (int i = 0; i < 2; i++) {
        int fid = tid + (i << 8);
        int r = fid >> 4, c = (fid & 15) << 2;
        *(float4*)&Qs[r][c] = *(const float4*)(g_Q + (q0 + r) * DMODEL + h * HDIM + c);
    }
    __syncthreads();
    float sc0[4] = {0, 0, 0, 0}, sc1[4] = {0, 0, 0, 0};
#pragma unroll
    for (int d4 = 0; d4 < 16; d4++) {
        float4 ka = *(const float4*)&K1s[lane][d4 << 2];
        float4 kb = *(const float4*)&K1s[lane + 32][d4 << 2];
#pragma unroll
        for (int r = 0; r < 4; r++) {
            float4 qv = *(const float4*)&Qs[r0 + r][d4 << 2];
            sc0[r] += qv.x * ka.x + qv.y * ka.y + qv.z * ka.z + qv.w * ka.w;
            sc1[r] += qv.x * kb.x + qv.y * kb.y + qv.z * kb.z + qv.w * kb.w;
        }
    }
#pragma unroll
    for (int r = 0; r < 4; r++) {
        float s0 = sc0[r], s1 = sc1[r];
        unsigned long long msk = 0ull;
#pragma unroll
        for (int it = 0; it < 8; it++) {
            float bv; int bi;
            if (s0 >= s1) { bv = s0; bi = lane; }       // tie -> lower index
            else          { bv = s1; bi = lane + 32; }
#pragma unroll
            for (int off = 16; off; off >>= 1) {
                float ov = __shfl_xor_sync(0xffffffffu, bv, off);
                int   oi = __shfl_xor_sync(0xffffffffu, bi, off);
                if (ov > bv || (ov == bv && oi < bi)) { bv = ov; bi = oi; }
            }
            msk |= 1ull << bi;
            if (bi == lane) s0 = NEG_INF;
            else if (bi == lane + 32) s1 = NEG_INF;
        }
        if (lane == 0) g_sel[h * S_LEN + q0 + r0 + r] = msk;
    }
}

// ---------------- masked flash attention ----------------
// grid (16 heads, 64 q-tiles of 32) [reversed for load balance], 256 threads.
// mask(q,k): k<=q && (q-k<512 || block-bit(k>>5) set). Skip kv-tiles not needed
// by any row (outside window union and not in union of selection bitmasks).
__global__ void __launch_bounds__(256) attn_kernel() {
    const int h = blockIdx.x;
    const int qt = 63 - blockIdx.y;          // heavy tiles first
    const int q0 = qt << 5;
    __shared__ float Qs[32][68];
    __shared__ float Ks[32][68];
    __shared__ float Vs[32][68];
    __shared__ float Ps[32][33];
    __shared__ unsigned long long Ssel[32];
    __shared__ unsigned long long s_uni;
    const int tid = threadIdx.x, lane = tid & 31, wid = tid >> 5;
    const int r0 = wid << 2;

#pragma unroll
    for (int i = 0; i < 2; i++) {
        int fid = tid + (i << 8);
        int r = fid >> 4, c = (fid & 15) << 2;
        *(float4*)&Qs[r][c] = *(const float4*)(g_Q + (q0 + r) * DMODEL + h * HDIM + c);
    }
    if (tid < 32) Ssel[tid] = g_sel[h * S_LEN + q0 + tid];
    __syncthreads();
    if (tid == 0) {
        unsigned long long u = 0;
        for (int r = 0; r < 32; r++) u |= Ssel[r];
        s_uni = u;
    }
    __syncthreads();
    const unsigned long long uni = s_uni;
    const int wlo = (q0 >= 512) ? ((q0 - 511) >> 5) : 0;

    float m[4], l[4];
    float2 acc[4];
#pragma unroll
    for (int r = 0; r < 4; r++) { m[r] = NEG_INF; l[r] = 0.f; acc[r] = make_float2(0.f, 0.f); }

    for (int tk = 0; tk <= qt; tk++) {
        if (tk < wlo && !((uni >> tk) & 1ull)) continue;   // block-uniform skip
        __syncthreads();
#pragma unroll
        for (int i = 0; i < 2; i++) {
            int fid = tid + (i << 8);
            int r = fid >> 4, c = (fid & 15) << 2;
            int gro = ((tk << 5) + r) * DMODEL + h * HDIM + c;
            *(float4*)&Ks[r][c] = *(const float4*)(g_K + gro);
            *(float4*)&Vs[r][c] = *(const float4*)(g_V + gro);
        }
        __syncthreads();

        float s[4] = {0, 0, 0, 0};
#pragma unroll
        for (int d4 = 0; d4 < 16; d4++) {
            float4 kv = *(const float4*)&Ks[lane][d4 << 2];
#pragma unroll
            for (int r = 0; r < 4; r++) {
                float4 qv = *(const float4*)&Qs[r0 + r][d4 << 2];
                s[r] += qv.x * kv.x + qv.y * kv.y + qv.z * kv.z + qv.w * kv.w;
            }
        }
        const int k = (tk << 5) + lane;
#pragma unroll
        for (int r = 0; r < 4; r++) {
            const int q = q0 + r0 + r;
            bool ok = (k <= q) && ((q - k) < 512 || ((Ssel[r0 + r] >> tk) & 1ull));
            float sv = ok ? s[r] : NEG_INF;
            float mx = sv;
#pragma unroll
            for (int off = 16; off; off >>= 1)
                mx = fmaxf(mx, __shfl_xor_sync(0xffffffffu, mx, off));
            float mn = fmaxf(m[r], mx);
            float p, cf;
            if (mn == NEG_INF) { p = 0.f; cf = 1.f; }
            else { cf = expf(m[r] - mn); p = expf(sv - mn); }
            m[r] = mn;
            float ps = p;
#pragma unroll
            for (int off = 16; off; off >>= 1)
                ps += __shfl_xor_sync(0xffffffffu, ps, off);
            l[r] = l[r] * cf + ps;
            acc[r].x *= cf; acc[r].y *= cf;
            Ps[r0 + r][lane] = p;
        }
        __syncwarp();
#pragma unroll 8
        for (int kk = 0; kk < 32; kk++) {
            float2 v = *(const float2*)&Vs[kk][lane << 1];
#pragma unroll
            for (int r = 0; r < 4; r++) {
                float p = Ps[r0 + r][kk];
                acc[r].x = fmaf(p, v.x, acc[r].x);
                acc[r].y = fmaf(p, v.y, acc[r].y);
            }
        }
    }
#pragma unroll
    for (int r = 0; r < 4; r++) {
        float inv = 1.0f / l[r];   // diagonal always attended -> l >= 1
        float2 o = make_float2(acc[r].x * inv, acc[r].y * inv);
        *(float2*)(g_AO + (q0 + r0 + r) * DMODEL + h * HDIM + (lane << 1)) = o;
    }
}

// ---------------- launch ----------------
extern "C" void kernel_launch(void* const* d_in, const int* in_sizes, int n_in,
                              void* d_out, int out_size) {
    const float* x    = (const float*)d_in[0];
    const float* Wq   = (const float*)d_in[1];
    const float* Wk   = (const float*)d_in[2];
    const float* Wv   = (const float*)d_in[3];
    const float* Wo   = (const float*)d_in[4];
    const float* lod1 = (const float*)d_in[5];
    // d_in[6..8] (v_lod1, k_lod2, v_lod2) are dead in the reference.

    gemm_qkv_kernel<<<dim3(16, 16, 3), 256>>>(x, Wq, Wk, Wv);
    rope_kernel<<<4096, 256>>>();
    k1_kernel<<<dim3(16, 16), 256>>>(lod1);
    top8_kernel<<<dim3(16, 64), 256>>>();
    attn_kernel<<<dim3(16, 64), 256>>>();
    gemm_out_kernel<<<dim3(16, 16), 256>>>(Wo, (float*)d_out);
}

// round 12
// speedup vs baseline: 1.7631x; 1.3695x over previous
#include <cuda_runtime.h>
#include <cuda_bf16.h>
#include <math.h>

// B=1, S=2048, D_MODEL=1024, H=16, D=64, G=32, n1=64, TOP1=8, WIN=512.
// LOD2 provably no-op -> top-8 over scores1. GEMMs + attention QK/PV on
// tensor cores via bf16x2 hi/lo split (3 mmas, drop lo*lo ~2^-16).

#define S_LEN 2048
#define DMODEL 1024
#define NHEAD 16
#define HDIM 64
#define NEG_INF (__int_as_float(0xff800000))

// ---------------- scratch (device globals; no allocs allowed) ----------------
__device__ float g_Q[S_LEN * DMODEL];
__device__ float g_K[S_LEN * DMODEL];
__device__ float g_V[S_LEN * DMODEL];
__device__ float g_AO[S_LEN * DMODEL];
__device__ float g_K1[NHEAD * 64 * 64];
__device__ unsigned long long g_sel[NHEAD * S_LEN];
// packed bf16-pair layouts for attention mma:
//   Q/K: [(h*2048 + s)*32 + dpair]   (pairs along d)
//   V:   [(h*64 + d)*1024 + keypair] (pairs along keys)
__device__ unsigned g_Qh[NHEAD * S_LEN * 32];
__device__ unsigned g_Ql[NHEAD * S_LEN * 32];
__device__ unsigned g_Kh[NHEAD * S_LEN * 32];
__device__ unsigned g_Kl[NHEAD * S_LEN * 32];
__device__ unsigned g_Vh[NHEAD * HDIM * (S_LEN / 2)];
__device__ unsigned g_Vl[NHEAD * HDIM * (S_LEN / 2)];

// ---------------- bf16 split helpers ----------------
__device__ __forceinline__ void bsplit2(float x0, float x1,
                                        unsigned& hi, unsigned& lo) {
    __nv_bfloat16 h0 = __float2bfloat16(x0);
    __nv_bfloat16 h1 = __float2bfloat16(x1);
    __nv_bfloat16 l0 = __float2bfloat16(x0 - __bfloat162float(h0));
    __nv_bfloat16 l1 = __float2bfloat16(x1 - __bfloat162float(h1));
    hi = ((unsigned)__bfloat16_as_ushort(h1) << 16) | (unsigned)__bfloat16_as_ushort(h0);
    lo = ((unsigned)__bfloat16_as_ushort(l1) << 16) | (unsigned)__bfloat16_as_ushort(l0);
}

#define MMA_BF16(Cf, Au, Bu)                                                  \
    asm volatile(                                                             \
        "mma.sync.aligned.m16n8k16.row.col.f32.bf16.bf16.f32 "                \
        "{%0,%1,%2,%3}, {%4,%5,%6,%7}, {%8,%9}, {%0,%1,%2,%3};"               \
        : "+f"(Cf[0]), "+f"(Cf[1]), "+f"(Cf[2]), "+f"(Cf[3])                  \
        : "r"(Au[0]), "r"(Au[1]), "r"(Au[2]), "r"(Au[3]),                     \
          "r"(Bu[0]), "r"(Bu[1]))

// ---------------- tensor-core SGEMM (bf16x2 split) -- unchanged from R9 ------
__device__ __forceinline__ void sgemm_body(const float* __restrict__ A,
                                           const float* __restrict__ B,
                                           float* __restrict__ C) {
    __shared__ unsigned Ah[128][12], Al[128][12], Bh[64][12], Bl[64][12];
    const int tid = threadIdx.x;
    const int lane = tid & 31, warp = tid >> 5;
    const int wy = warp >> 1, wx = warp & 1;
    const int m0 = blockIdx.y * 128, n0 = blockIdx.x * 64;
    const int mw = wy * 32, nw = wx * 32;
    const int gr = tid >> 2;
    const int gc = (tid & 3) << 2;
    const int gu = (tid & 3) << 1;

    float acc[2][4][4];
#pragma unroll
    for (int i = 0; i < 2; i++)
#pragma unroll
        for (int j = 0; j < 4; j++)
#pragma unroll
            for (int e = 0; e < 4; e++) acc[i][j][e] = 0.f;

    float4 pa0, pa1, pb;
    pa0 = *(const float4*)(A + (m0 + gr) * 1024 + gc);
    pa1 = *(const float4*)(A + (m0 + 64 + gr) * 1024 + gc);
    pb  = *(const float4*)(B + (n0 + gr) * 1024 + gc);
    {
        unsigned h0, l0, h1, l1;
        bsplit2(pa0.x, pa0.y, h0, l0); bsplit2(pa0.z, pa0.w, h1, l1);
        *(uint2*)&Ah[gr][gu] = make_uint2(h0, h1);
        *(uint2*)&Al[gr][gu] = make_uint2(l0, l1);
        bsplit2(pa1.x, pa1.y, h0, l0); bsplit2(pa1.z, pa1.w, h1, l1);
        *(uint2*)&Ah[gr + 64][gu] = make_uint2(h0, h1);
        *(uint2*)&Al[gr + 64][gu] = make_uint2(l0, l1);
        bsplit2(pb.x, pb.y, h0, l0); bsplit2(pb.z, pb.w, h1, l1);
        *(uint2*)&Bh[gr][gu] = make_uint2(h0, h1);
        *(uint2*)&Bl[gr][gu] = make_uint2(l0, l1);
    }
    __syncthreads();

    const int g = lane >> 2, t = lane & 3;

    for (int kt = 0; kt < 1024; kt += 16) {
        const bool more = (kt + 16) < 1024;
        if (more) {
            pa0 = *(const float4*)(A + (m0 + gr) * 1024 + kt + 16 + gc);
            pa1 = *(const float4*)(A + (m0 + 64 + gr) * 1024 + kt + 16 + gc);
            pb  = *(const float4*)(B + (n0 + gr) * 1024 + kt + 16 + gc);
        }
        unsigned ah[2][4], al2[2][4], bh[4][2], bl2[4][2];
#pragma unroll
        for (int i = 0; i < 2; i++) {
            const int m = mw + i * 16 + g;
            ah[i][0] = Ah[m][t];      ah[i][1] = Ah[m + 8][t];
            ah[i][2] = Ah[m][t + 4];  ah[i][3] = Ah[m + 8][t + 4];
            al2[i][0] = Al[m][t];     al2[i][1] = Al[m + 8][t];
            al2[i][2] = Al[m][t + 4]; al2[i][3] = Al[m + 8][t + 4];
        }
#pragma unroll
        for (int j = 0; j < 4; j++) {
            const int n = nw + j * 8 + g;
            bh[j][0] = Bh[n][t];  bh[j][1] = Bh[n][t + 4];
            bl2[j][0] = Bl[n][t]; bl2[j][1] = Bl[n][t + 4];
        }
#pragma unroll
        for (int i = 0; i < 2; i++)
#pragma unroll
            for (int j = 0; j < 4; j++) {
                MMA_BF16(acc[i][j], ah[i], bh[j]);
                MMA_BF16(acc[i][j], al2[i], bh[j]);
                MMA_BF16(acc[i][j], ah[i], bl2[j]);
            }
        __syncthreads();
        if (more) {
            unsigned h0, l0, h1, l1;
            bsplit2(pa0.x, pa0.y, h0, l0); bsplit2(pa0.z, pa0.w, h1, l1);
            *(uint2*)&Ah[gr][gu] = make_uint2(h0, h1);
            *(uint2*)&Al[gr][gu] = make_uint2(l0, l1);
            bsplit2(pa1.x, pa1.y, h0, l0); bsplit2(pa1.z, pa1.w, h1, l1);
            *(uint2*)&Ah[gr + 64][gu] = make_uint2(h0, h1);
            *(uint2*)&Al[gr + 64][gu] = make_uint2(l0, l1);
            bsplit2(pb.x, pb.y, h0, l0); bsplit2(pb.z, pb.w, h1, l1);
            *(uint2*)&Bh[gr][gu] = make_uint2(h0, h1);
            *(uint2*)&Bl[gr][gu] = make_uint2(l0, l1);
            __syncthreads();
        }
    }

    const int col2 = (lane & 3) << 1;
#pragma unroll
    for (int i = 0; i < 2; i++)
#pragma unroll
        for (int j = 0; j < 4; j++) {
            float* cp = C + (m0 + mw + i * 16 + g) * 1024 + n0 + nw + j * 8 + col2;
            *(float2*)cp = make_float2(acc[i][j][0], acc[i][j][1]);
            *(float2*)(cp + 8 * 1024) = make_float2(acc[i][j][2], acc[i][j][3]);
        }
}

__global__ void __launch_bounds__(256, 2) gemm_qkv_kernel(const float* __restrict__ x,
                                                          const float* __restrict__ Wq,
                                                          const float* __restrict__ Wk,
                                                          const float* __restrict__ Wv) {
    const float* B = (blockIdx.z == 0) ? Wq : (blockIdx.z == 1 ? Wk : Wv);
    float* C = (blockIdx.z == 0) ? g_Q : (blockIdx.z == 1 ? g_K : g_V);
    sgemm_body(x, B, C);
}

__global__ void __launch_bounds__(256, 2) gemm_out_kernel(const float* __restrict__ Wo,
                                                          float* __restrict__ out) {
    sgemm_body(g_AO, Wo, out);
}

// ---------------- RoPE (in place) + fold SCALE into Q ----------------
__global__ void __launch_bounds__(256) rope_kernel() {
    int idx = blockIdx.x * 256 + threadIdx.x;
    int s = idx >> 9;
    int rem = idx & 511;
    int h = rem >> 5;
    int d = rem & 31;
    float expo = (2.0f * (float)d) / 64.0f;
    float inv = 1.0f / powf(10000.0f, expo);
    float ang = (float)s * inv;
    float c, sn;
    sincosf(ang, &sn, &c);
    int base = s * DMODEL + h * HDIM + d;
    float q0 = g_Q[base], q1 = g_Q[base + 32];
    g_Q[base]      = (q0 * c - q1 * sn) * 0.125f;
    g_Q[base + 32] = (q1 * c + q0 * sn) * 0.125f;
    float k0 = g_K[base], k1 = g_K[base + 32];
    g_K[base]      = k0 * c - k1 * sn;
    g_K[base + 32] = k1 * c + k0 * sn;
}

// ---------------- pack Q,K (post-rope) into bf16-pair frag layout -----------
__global__ void __launch_bounds__(256) pack_qk_kernel() {
    int idx = blockIdx.x * 256 + threadIdx.x;   // 2048*16*32 = 1M
    int dp = idx & 31;
    int s = idx >> 9, h = (idx >> 5) & 15;
    int src = s * DMODEL + h * HDIM + dp * 2;
    int dst = ((h << 11) + s) * 32 + dp;
    float2 q = *(const float2*)(g_Q + src);
    float2 k = *(const float2*)(g_K + src);
    unsigned hi, lo;
    bsplit2(q.x, q.y, hi, lo); g_Qh[dst] = hi; g_Ql[dst] = lo;
    bsplit2(k.x, k.y, hi, lo); g_Kh[dst] = hi; g_Kl[dst] = lo;
}

// ---------------- pack V into [h][d][keypair] (smem transpose) --------------
__global__ void __launch_bounds__(256) pack_v_kernel() {
    const int h = blockIdx.x, kc = blockIdx.y;   // 128-key chunk
    __shared__ float Vsm[128][65];
    const int tid = threadIdx.x;
#pragma unroll
    for (int i = 0; i < 32; i++) {
        int fid = tid + (i << 8);
        int row = fid >> 6, col = fid & 63;
        Vsm[row][col] = g_V[(kc * 128 + row) * DMODEL + h * HDIM + col];
    }
    __syncthreads();
#pragma unroll
    for (int i = 0; i < 16; i++) {
        int fid = tid + (i << 8);
        int d = fid >> 6, kp = fid & 63;
        unsigned hi, lo;
        bsplit2(Vsm[2 * kp][d], Vsm[2 * kp + 1][d], hi, lo);
        int dst = ((h << 6) + d) * 1024 + (kc << 6) + kp;
        g_Vh[dst] = hi; g_Vl[dst] = lo;
    }
}

// ---------------- LOD1 projection (unchanged) ----------------
__global__ void __launch_bounds__(256) k1_kernel(const float* __restrict__ lod1) {
    const int h = blockIdx.x, bg = blockIdx.y;
    __shared__ float Ksm[4][2048];
    const int tid = threadIdx.x;
#pragma unroll
    for (int i = 0; i < 8; i++) {
        int fid = tid + (i << 8);
        int rr = fid >> 4;
        int c = (fid & 15) << 2;
        float4 v = *(const float4*)(g_K + (bg * 128 + rr) * DMODEL + h * HDIM + c);
        *(float4*)&Ksm[rr >> 5][((rr & 31) << 6) + c] = v;
    }
    __syncthreads();
    const int bl = tid >> 6, o = tid & 63;
    const float4* lp = (const float4*)(lod1 + o * 2048);
    const float4* kp = (const float4*)&Ksm[bl][0];
    float acc = 0.f;
#pragma unroll 4
    for (int j = 0; j < 512; j++) {
        float4 a = lp[j], b = kp[j];
        acc += a.x * b.x + a.y * b.y + a.z * b.z + a.w * b.w;
    }
    g_K1[(h * 64 + (bg << 2) + bl) * 64 + o] = acc;
}

// ---------------- scores1 + top-8 -> 64-bit block mask (unchanged) ----------
__global__ void __launch_bounds__(256) top8_kernel() {
    const int h = blockIdx.x;
    const int q0 = blockIdx.y << 5;
    __shared__ float K1s[64][68];
    __shared__ float Qs[32][68];
    const int tid = threadIdx.x, lane = tid & 31, wid = tid >> 5;
    const int r0 = wid << 2;
#pragma unroll
    for (int i = 0; i < 4; i++) {
        int fid = tid + (i << 8);
        int r = fid >> 4, c = (fid & 15) << 2;
        *(float4*)&K1s[r][c] = *(const float4*)(g_K1 + (h * 64 + r) * 64 + c);
    }
#pragma unroll
    for (int i = 0; i < 2; i++) {
        int fid = tid + (i << 8);
        int r = fid >> 4, c = (fid & 15) << 2;
        *(float4*)&Qs[r][c] = *(const float4*)(g_Q + (q0 + r) * DMODEL + h * HDIM + c);
    }
    __syncthreads();
    float sc0[4] = {0, 0, 0, 0}, sc1[4] = {0, 0, 0, 0};
#pragma unroll
    for (int d4 = 0; d4 < 16; d4++) {
        float4 ka = *(const float4*)&K1s[lane][d4 << 2];
        float4 kb = *(const float4*)&K1s[lane + 32][d4 << 2];
#pragma unroll
        for (int r = 0; r < 4; r++) {
            float4 qv = *(const float4*)&Qs[r0 + r][d4 << 2];
            sc0[r] += qv.x * ka.x + qv.y * ka.y + qv.z * ka.z + qv.w * ka.w;
            sc1[r] += qv.x * kb.x + qv.y * kb.y + qv.z * kb.z + qv.w * kb.w;
        }
    }
#pragma unroll
    for (int r = 0; r < 4; r++) {
        float s0 = sc0[r], s1 = sc1[r];
        unsigned long long msk = 0ull;
#pragma unroll
        for (int it = 0; it < 8; it++) {
            float bv; int bi;
            if (s0 >= s1) { bv = s0; bi = lane; }
            else          { bv = s1; bi = lane + 32; }
#pragma unroll
            for (int off = 16; off; off >>= 1) {
                float ov = __shfl_xor_sync(0xffffffffu, bv, off);
                int   oi = __shfl_xor_sync(0xffffffffu, bi, off);
                if (ov > bv || (ov == bv && oi < bi)) { bv = ov; bi = oi; }
            }
            msk |= 1ull << bi;
            if (bi == lane) s0 = NEG_INF;
            else if (bi == lane + 32) s1 = NEG_INF;
        }
        if (lane == 0) g_sel[h * S_LEN + q0 + r0 + r] = msk;
    }
}

// ---------------- tensor-core masked flash attention ----------------
// Block = 64 queries x 1 head; 4 warps x 16 queries. K/V tiles of 32 keys in
// smem (bf16x2 packed). QK and PV via m16n8k16 (3-mma split). Softmax fully
// in fragment registers (quad shuffles). Per-warp tile skip via window +
// 16-row selection union.
__global__ void __launch_bounds__(128) attn_kernel() {
    const int h = blockIdx.x;
    const int qb = 31 - blockIdx.y;          // heavy blocks first
    const int q0 = qb << 6;
    const int tid = threadIdx.x, lane = tid & 31, w = tid >> 5;
    const int g = lane >> 2, t = lane & 3;

    __shared__ unsigned Khs[32][36], Kls[32][36];   // [key][dpair], stride 36
    __shared__ unsigned Vhs[64][20], Vls[64][20];   // [d][keypair], stride 20
    __shared__ unsigned long long Ssel[64];
    __shared__ unsigned long long s_need[4];

    if (tid < 64) Ssel[tid] = g_sel[h * S_LEN + q0 + tid];
    __syncthreads();

    const int rw0 = q0 + (w << 4);               // warp's first query row
    const int qtw = (rw0 + 15) >> 5;             // warp's last causal tile
    const int wlow = (rw0 > 511) ? ((rw0 - 511) >> 5) : 0;
    unsigned long long uw = 0;
#pragma unroll
    for (int r = 0; r < 16; r++) uw |= Ssel[(w << 4) + r];
    const unsigned long long wmask = (qtw >= 63) ? ~0ull : ((1ull << (qtw + 1)) - 1ull);
    const unsigned long long winm = wmask ^ ((1ull << wlow) - 1ull);
    const unsigned long long aw = winm | (uw & wmask);
    if (lane == 0) s_need[w] = aw;
    __syncthreads();
    const unsigned long long need = s_need[0] | s_need[1] | s_need[2] | s_need[3];
    const int qtmax = (q0 + 63) >> 5;

    // Q fragments (A of m16n8k16), 4 k-steps over D=64
    unsigned qh[4][4], ql[4][4];
    {
        const unsigned* Qh = g_Qh + ((h << 11) + rw0) * 32;
        const unsigned* Ql = g_Ql + ((h << 11) + rw0) * 32;
#pragma unroll
        for (int s = 0; s < 4; s++) {
            int c0 = s * 8 + t;
            qh[s][0] = Qh[g * 32 + c0];       qh[s][1] = Qh[(g + 8) * 32 + c0];
            qh[s][2] = Qh[g * 32 + c0 + 4];   qh[s][3] = Qh[(g + 8) * 32 + c0 + 4];
            ql[s][0] = Ql[g * 32 + c0];       ql[s][1] = Ql[(g + 8) * 32 + c0];
            ql[s][2] = Ql[g * 32 + c0 + 4];   ql[s][3] = Ql[(g + 8) * 32 + c0 + 4];
        }
    }

    float acc[8][4];
#pragma unroll
    for (int jd = 0; jd < 8; jd++)
#pragma unroll
        for (int e = 0; e < 4; e++) acc[jd][e] = 0.f;
    float m0 = NEG_INF, m1 = NEG_INF, l0 = 0.f, l1 = 0.f;

    const int r0 = rw0 + g, r1 = r0 + 8;
    const unsigned long long sel0 = Ssel[(w << 4) + g];
    const unsigned long long sel1 = Ssel[(w << 4) + g + 8];

    for (int tk = 0; tk <= qtmax; tk++) {
        if (!((need >> tk) & 1ull)) continue;
        __syncthreads();
        // load K tile (32 keys x 32 dpairs) + V tile (64 d x 16 keypairs)
        {
            const uint4* skh = (const uint4*)(g_Kh + ((h << 11) + (tk << 5)) * 32);
            const uint4* skl = (const uint4*)(g_Kl + ((h << 11) + (tk << 5)) * 32);
#pragma unroll
            for (int i = 0; i < 2; i++) {
                int idx = (tid << 1) + i;          // 0..255
                int key = idx >> 3, c4 = (idx & 7) << 2;
                *(uint4*)&Khs[key][c4] = skh[idx];
                *(uint4*)&Kls[key][c4] = skl[idx];
            }
#pragma unroll
            for (int i = 0; i < 2; i++) {
                int idx = (tid << 1) + i;          // 0..255
                int d = idx >> 2, c4 = (idx & 3) << 2;
                int off = ((h << 6) + d) * 1024 + (tk << 4) + c4;
                *(uint4*)&Vhs[d][c4] = *(const uint4*)(g_Vh + off);
                *(uint4*)&Vls[d][c4] = *(const uint4*)(g_Vl + off);
            }
        }
        __syncthreads();
        if (!((aw >> tk) & 1ull)) continue;

        // ---- QK: scores for 16 rows x 32 keys ----
        float sc[4][4];
#pragma unroll
        for (int j = 0; j < 4; j++)
#pragma unroll
            for (int e = 0; e < 4; e++) sc[j][e] = 0.f;
#pragma unroll
        for (int s = 0; s < 4; s++)
#pragma unroll
            for (int j = 0; j < 4; j++) {
                unsigned bh[2] = {Khs[j * 8 + g][s * 8 + t], Khs[j * 8 + g][s * 8 + t + 4]};
                unsigned bl[2] = {Kls[j * 8 + g][s * 8 + t], Kls[j * 8 + g][s * 8 + t + 4]};
                MMA_BF16(sc[j], qh[s], bh);
                MMA_BF16(sc[j], ql[s], bh);
                MMA_BF16(sc[j], qh[s], bl);
            }

        // ---- mask ----
        const int kb = tk << 5;
        const bool full = (kb + 31 <= rw0) && ((rw0 + 15 - kb) < 512);
        if (!full) {
            const bool sb0 = (sel0 >> tk) & 1ull, sb1 = (sel1 >> tk) & 1ull;
#pragma unroll
            for (int j = 0; j < 4; j++) {
                int k0 = kb + j * 8 + 2 * t, k1 = k0 + 1;
                if (!((k0 <= r0) && (k0 >= r0 - 511 || sb0))) sc[j][0] = NEG_INF;
                if (!((k1 <= r0) && (k1 >= r0 - 511 || sb0))) sc[j][1] = NEG_INF;
                if (!((k0 <= r1) && (k0 >= r1 - 511 || sb1))) sc[j][2] = NEG_INF;
                if (!((k1 <= r1) && (k1 >= r1 - 511 || sb1))) sc[j][3] = NEG_INF;
            }
        }

        // ---- online softmax in fragments ----
        float mx0 = sc[0][0], mx1 = sc[0][2];
#pragma unroll
        for (int j = 0; j < 4; j++) {
            mx0 = fmaxf(mx0, fmaxf(sc[j][0], sc[j][1]));
            mx1 = fmaxf(mx1, fmaxf(sc[j][2], sc[j][3]));
        }
        mx0 = fmaxf(mx0, __shfl_xor_sync(0xffffffffu, mx0, 1));
        mx0 = fmaxf(mx0, __shfl_xor_sync(0xffffffffu, mx0, 2));
        mx1 = fmaxf(mx1, __shfl_xor_sync(0xffffffffu, mx1, 1));
        mx1 = fmaxf(mx1, __shfl_xor_sync(0xffffffffu, mx1, 2));
        float mn0 = fmaxf(m0, mx0), mn1 = fmaxf(m1, mx1);
        float cf0 = (mn0 == NEG_INF) ? 1.f : expf(m0 - mn0);
        float cf1 = (mn1 == NEG_INF) ? 1.f : expf(m1 - mn1);
        float p[4][4];
        float sum0 = 0.f, sum1 = 0.f;
#pragma unroll
        for (int j = 0; j < 4; j++) {
            p[j][0] = (mn0 == NEG_INF) ? 0.f : expf(sc[j][0] - mn0);
            p[j][1] = (mn0 == NEG_INF) ? 0.f : expf(sc[j][1] - mn0);
            p[j][2] = (mn1 == NEG_INF) ? 0.f : expf(sc[j][2] - mn1);
            p[j][3] = (mn1 == NEG_INF) ? 0.f : expf(sc[j][3] - mn1);
            sum0 += p[j][0] + p[j][1];
            sum1 += p[j][2] + p[j][3];
        }
        sum0 += __shfl_xor_sync(0xffffffffu, sum0, 1);
        sum0 += __shfl_xor_sync(0xffffffffu, sum0, 2);
        sum1 += __shfl_xor_sync(0xffffffffu, sum1, 1);
        sum1 += __shfl_xor_sync(0xffffffffu, sum1, 2);
        l0 = l0 * cf0 + sum0;
        l1 = l1 * cf1 + sum1;
        m0 = mn0; m1 = mn1;
#pragma unroll
        for (int jd = 0; jd < 8; jd++) {
            acc[jd][0] *= cf0; acc[jd][1] *= cf0;
            acc[jd][2] *= cf1; acc[jd][3] *= cf1;
        }

        // ---- pack P into A fragments (direct C->A mapping, no shuffles) ----
        unsigned ph[2][4], pl[2][4];
#pragma unroll
        for (int s = 0; s < 2; s++) {
            bsplit2(p[2 * s][0],     p[2 * s][1],     ph[s][0], pl[s][0]);
            bsplit2(p[2 * s][2],     p[2 * s][3],     ph[s][1], pl[s][1]);
            bsplit2(p[2 * s + 1][0], p[2 * s + 1][1], ph[s][2], pl[s][2]);
            bsplit2(p[2 * s + 1][2], p[2 * s + 1][3], ph[s][3], pl[s][3]);
        }

        // ---- PV: acc += P @ V ----
#pragma unroll
        for (int jd = 0; jd < 8; jd++)
#pragma unroll
            for (int s = 0; s < 2; s++) {
                unsigned bvh[2] = {Vhs[jd * 8 + g][(s << 3) + t], Vhs[jd * 8 + g][(s << 3) + t + 4]};
                unsigned bvl[2] = {Vls[jd * 8 + g][(s << 3) + t], Vls[jd * 8 + g][(s << 3) + t + 4]};
                MMA_BF16(acc[jd], ph[s], bvh);
                MMA_BF16(acc[jd], pl[s], bvh);
                MMA_BF16(acc[jd], ph[s], bvl);
            }
    }

    // ---- output ----
    const float inv0 = 1.f / l0, inv1 = 1.f / l1;   // diagonal attended -> l>=1
#pragma unroll
    for (int jd = 0; jd < 8; jd++) {
        float* o0 = g_AO + r0 * DMODEL + h * HDIM + jd * 8 + 2 * t;
        *(float2*)o0 = make_float2(acc[jd][0] * inv0, acc[jd][1] * inv0);
        float* o1 = g_AO + r1 * DMODEL + h * HDIM + jd * 8 + 2 * t;
        *(float2*)o1 = make_float2(acc[jd][2] * inv1, acc[jd][3] * inv1);
    }
}

// ---------------- launch ----------------
extern "C" void kernel_launch(void* const* d_in, const int* in_sizes, int n_in,
                              void* d_out, int out_size) {
    const float* x    = (const float*)d_in[0];
    const float* Wq   = (const float*)d_in[1];
    const float* Wk   = (const float*)d_in[2];
    const float* Wv   = (const float*)d_in[3];
    const float* Wo   = (const float*)d_in[4];
    const float* lod1 = (const float*)d_in[5];

    gemm_qkv_kernel<<<dim3(16, 16, 3), 256>>>(x, Wq, Wk, Wv);
    rope_kernel<<<4096, 256>>>();
    pack_qk_kernel<<<4096, 256>>>();
    pack_v_kernel<<<dim3(16, 16), 256>>>();
    k1_kernel<<<dim3(16, 16), 256>>>(lod1);
    top8_kernel<<<dim3(16, 64), 256>>>();
    attn_kernel<<<dim3(16, 32), 128>>>();
    gemm_out_kernel<<<dim3(16, 16), 256>>>(Wo, (float*)d_out);
}